// round 1
// baseline (speedup 1.0000x reference)
#include <cuda_runtime.h>
#include <math.h>

#define Bk 2
#define Tk 128
#define Dk 384
#define Nk (Bk*Tk)        // 256 token rows
#define Hk 1024
#define Ck 256
#define NITER 4
#define PADk (Dk-1)       // 383
#define Sk (2*Dk-1)       // 767 shifts
#define EPSk 1e-6f
#define TEMPERk 10.0f

// ---------------- scratch (no allocations allowed) ----------------
__device__ float          g_xele[Nk*Dk];
__device__ float          g_h[Nk*Hk];
__device__ unsigned char  g_mask[Nk*Hk];
__device__ int            g_selidx[Nk*Ck];
__device__ float          g_selval[Nk*Ck];
__device__ float          g_partial[NITER*Nk];
__device__ float          g_denom[1];

// orderable key: larger float -> larger unsigned
__device__ __forceinline__ unsigned fkey(float f) {
    unsigned u = __float_as_uint(f);
    return (u & 0x80000000u) ? ~u : (u | 0x80000000u);
}

// ================= kernel 1: shift/argmax/attn -> x_ele =================
__global__ __launch_bounds__(256) void k_xele(const float* __restrict__ x,
                                              const float* __restrict__ y) {
    int row = blockIdx.x;
    int t = threadIdx.x;
    __shared__ float xs[Dk], ys[Dk], xa[Dk];
    __shared__ float red[256];
    __shared__ int   redi[256];

    const float* xr = x + (size_t)row * Dk;
    const float* yr = y + (size_t)row * Dk;
    for (int i = t; i < Dk; i += 256) { xs[i] = xr[i]; ys[i] = yr[i]; }
    __syncthreads();

    // qn = ||y||
    float s = 0.f;
    for (int i = t; i < Dk; i += 256) { float v = ys[i]; s += v * v; }
    red[t] = s; __syncthreads();
    for (int o = 128; o > 0; o >>= 1) { if (t < o) red[t] += red[t + o]; __syncthreads(); }
    float qn = sqrtf(red[0]);
    __syncthreads();

    // shifts: sim + argmax (first occurrence of max, like jnp.argmax)
    float bestv = -INFINITY; int bests = 0x7fffffff;
    for (int sft = t; sft < Sk; sft += 256) {
        int u0 = sft - PADk; if (u0 < 0) u0 = 0;
        int u1 = sft;        if (u1 > Dk - 1) u1 = Dk - 1;
        float dot = 0.f, ss = 0.f;
        int off = PADk - sft;
        for (int u = u0; u <= u1; ++u) {
            float xv = xs[u];
            dot += xv * ys[u + off];
            ss  += xv * xv;
        }
        float sim = dot / (qn * sqrtf(ss) + EPSk);
        if (isnan(sim)) sim = 0.f;
        if (sim > bestv || (sim == bestv && sft < bests)) { bestv = sim; bests = sft; }
    }
    red[t] = bestv; redi[t] = bests; __syncthreads();
    for (int o = 128; o > 0; o >>= 1) {
        if (t < o) {
            float vo = red[t + o]; int io = redi[t + o];
            if (vo > red[t] || (vo == red[t] && io < redi[t])) { red[t] = vo; redi[t] = io; }
        }
        __syncthreads();
    }
    int theta = redi[0];
    __syncthreads();
    int shift = theta - PADk;   // x_opt[j] = x[j+shift] (0 if OOB)

    // ||x_opt||
    float ns = 0.f;
    for (int j = t; j < Dk; j += 256) {
        int u = j + shift;
        float v = (u >= 0 && u < Dk) ? xs[u] : 0.f;
        ns += v * v;
    }
    red[t] = ns; __syncthreads();
    for (int o = 128; o > 0; o >>= 1) { if (t < o) red[t] += red[t + o]; __syncthreads(); }
    float dn = sqrtf(red[0]) * qn + EPSk;
    __syncthreads();

    // softmax((x_opt*y/dn)/TEMPER) over D
    float zmax = -INFINITY;
    for (int j = t; j < Dk; j += 256) {
        int u = j + shift;
        float v = (u >= 0 && u < Dk) ? xs[u] : 0.f;
        float z = (v * ys[j] / dn) / TEMPERk;
        zmax = fmaxf(zmax, z);
    }
    red[t] = zmax; __syncthreads();
    for (int o = 128; o > 0; o >>= 1) { if (t < o) red[t] = fmaxf(red[t], red[t + o]); __syncthreads(); }
    float m = red[0];
    __syncthreads();

    float esum = 0.f;
    for (int j = t; j < Dk; j += 256) {
        int u = j + shift;
        float v = (u >= 0 && u < Dk) ? xs[u] : 0.f;
        float z = (v * ys[j] / dn) / TEMPERk;
        float e = expf(z - m);
        esum += e;
        xa[j] = v * e;     // divide by sum later
    }
    red[t] = esum; __syncthreads();
    for (int o = 128; o > 0; o >>= 1) { if (t < o) red[t] += red[t + o]; __syncthreads(); }
    float ssum = red[0];
    __syncthreads();
    for (int j = t; j < Dk; j += 256) xa[j] = xa[j] / ssum;  // x_attn
    __syncthreads();

    // reverse shift: x_ele[j] = x_attn[j - shift]
    float* xe = g_xele + (size_t)row * Dk;
    for (int j = t; j < Dk; j += 256) {
        int u = j - shift;
        xe[j] = (u >= 0 && u < Dk) ? xa[u] : 0.f;
    }
}

// ================= kernel 2: h = x_ele @ W_enc + b_enc =================
#define RPB 4
__global__ __launch_bounds__(256) void k_enc(const float* __restrict__ We,
                                             const float* __restrict__ be) {
    int rb = blockIdx.x;           // 64 blocks of 4 rows
    int t = threadIdx.x;           // 256
    __shared__ float xs[RPB * Dk];
    for (int i = t; i < RPB * Dk; i += 256) xs[i] = g_xele[(size_t)rb * RPB * Dk + i];
    __syncthreads();

    float acc[RPB][4];
    int c0 = t, c1 = t + 256, c2 = t + 512, c3 = t + 768;
    float b0 = be[c0], b1 = be[c1], b2 = be[c2], b3 = be[c3];
    #pragma unroll
    for (int r = 0; r < RPB; ++r) { acc[r][0] = b0; acc[r][1] = b1; acc[r][2] = b2; acc[r][3] = b3; }

    for (int k = 0; k < Dk; ++k) {
        const float* wr = We + (size_t)k * Hk;
        float w0 = wr[c0], w1 = wr[c1], w2 = wr[c2], w3 = wr[c3];
        #pragma unroll
        for (int r = 0; r < RPB; ++r) {
            float xv = xs[r * Dk + k];
            acc[r][0] += xv * w0; acc[r][1] += xv * w1;
            acc[r][2] += xv * w2; acc[r][3] += xv * w3;
        }
    }
    #pragma unroll
    for (int r = 0; r < RPB; ++r) {
        float* hr = g_h + (size_t)(rb * RPB + r) * Hk;
        hr[c0] = acc[r][0]; hr[c1] = acc[r][1]; hr[c2] = acc[r][2]; hr[c3] = acc[r][3];
    }
}

// ================= kernel 3: denom = count(y != 0) =================
__global__ __launch_bounds__(1024) void k_denom(const float* __restrict__ y) {
    __shared__ int red[1024];
    int t = threadIdx.x;
    int c = 0;
    for (int i = t; i < Nk * Dk; i += 1024) c += (y[i] != 0.0f);
    red[t] = c; __syncthreads();
    for (int o = 512; o > 0; o >>= 1) { if (t < o) red[t] += red[t + o]; __syncthreads(); }
    if (t == 0) g_denom[0] = (float)red[0];
}

// ================= kernel 4: masked exact top-256 via radix select =================
__global__ __launch_bounds__(256) void k_topk(int it) {
    int row = blockIdx.x;
    int t = threadIdx.x;
    __shared__ float    hv[Hk];
    __shared__ unsigned kv[Hk];
    __shared__ int      cnt[256];
    __shared__ int      sc[256];
    __shared__ unsigned sh_prefix;
    __shared__ int      sh_k;

    const float* hr = g_h + (size_t)row * Hk;
    unsigned char* mr = g_mask + (size_t)row * Hk;

    for (int i = t; i < Hk; i += 256) {
        float v = hr[i];
        if (it > 0 && mr[i]) v = 1e-10f;
        hv[i] = v;
        kv[i] = fkey(v);
    }
    __syncthreads();

    // radix select: key of the 256th largest + rank among equals
    unsigned prefix = 0, pmask = 0;
    int k = Ck;
    for (int pass = 3; pass >= 0; --pass) {
        int sb = pass * 8;
        cnt[t] = 0; __syncthreads();
        for (int i = t; i < Hk; i += 256) {
            unsigned u = kv[i];
            if ((u & pmask) == prefix) atomicAdd(&cnt[(u >> sb) & 0xff], 1);
        }
        __syncthreads();
        if (t == 0) {
            int kk = k; int b = 255;
            for (; b > 0; --b) { if (kk <= cnt[b]) break; kk -= cnt[b]; }
            sh_prefix = prefix | ((unsigned)b << sb);
            sh_k = kk;
        }
        __syncthreads();
        prefix = sh_prefix; k = sh_k;
        pmask |= (0xffu << sb);
        __syncthreads();
    }
    unsigned Tkey = prefix;   // key of 256th largest; k = # of equals to take (by smallest index)

    // per-thread 4 contiguous elements
    int i0 = t * 4;
    unsigned u4[4]; float v4[4];
    #pragma unroll
    for (int q = 0; q < 4; ++q) { u4[q] = kv[i0 + q]; v4[q] = hv[i0 + q]; }
    int eq[4], gt[4];
    #pragma unroll
    for (int q = 0; q < 4; ++q) { eq[q] = (u4[q] == Tkey); gt[q] = (u4[q] > Tkey); }

    // index-ordered rank among equals
    int eqc = eq[0] + eq[1] + eq[2] + eq[3];
    sc[t] = eqc; __syncthreads();
    for (int o = 1; o < 256; o <<= 1) {
        int add = (t >= o) ? sc[t - o] : 0;
        __syncthreads();
        sc[t] += add;
        __syncthreads();
    }
    int eqbase = sc[t] - eqc;
    __syncthreads();

    int flag[4]; int le = 0;
    #pragma unroll
    for (int q = 0; q < 4; ++q) {
        flag[q] = gt[q] || (eq[q] && (eqbase + le) < k);
        le += eq[q];
    }

    // ordered compaction of selected (ascending index)
    int fc = flag[0] + flag[1] + flag[2] + flag[3];
    sc[t] = fc; __syncthreads();
    for (int o = 1; o < 256; o <<= 1) {
        int add = (t >= o) ? sc[t - o] : 0;
        __syncthreads();
        sc[t] += add;
        __syncthreads();
    }
    int base = sc[t] - fc;

    int p = base;
    int* si = g_selidx + (size_t)row * Ck;
    float* sv = g_selval + (size_t)row * Ck;
    #pragma unroll
    for (int q = 0; q < 4; ++q) {
        if (flag[q]) { si[p] = i0 + q; sv[p] = v4[q]; ++p; }
    }
    // update union mask (iter 0 overwrites -> no reset needed between graph replays)
    #pragma unroll
    for (int q = 0; q < 4; ++q) {
        if (it == 0) mr[i0 + q] = (unsigned char)flag[q];
        else if (flag[q]) mr[i0 + q] = 1;
    }
}

// ================= kernel 5: sparse decode + masked-MSE partial =================
__global__ __launch_bounds__(384) void k_dec(const float* __restrict__ Wd,
                                             const float* __restrict__ bd,
                                             const float* __restrict__ x,
                                             const float* __restrict__ y,
                                             float* __restrict__ out, int it) {
    int row = blockIdx.x;
    int t = threadIdx.x; // 384
    __shared__ int   si[Ck];
    __shared__ float sv[Ck];
    __shared__ float red[512];
    if (t < Ck) { si[t] = g_selidx[(size_t)row * Ck + t]; sv[t] = g_selval[(size_t)row * Ck + t]; }
    __syncthreads();

    float acc = bd[t];
    #pragma unroll 4
    for (int i = 0; i < Ck; ++i) {
        acc += sv[i] * Wd[(size_t)si[i] * Dk + t];
    }
    out[((size_t)it * Nk + row) * Dk + t] = acc;

    float yv = y[(size_t)row * Dk + t];
    float xv = x[(size_t)row * Dk + t];
    float df = acc - xv;
    float d = (yv != 0.0f) ? df * df : 0.0f;

    red[t] = d; if (t < 128) red[Dk + t] = 0.f;
    __syncthreads();
    for (int o = 256; o > 0; o >>= 1) { if (t < o) red[t] += red[t + o]; __syncthreads(); }
    if (t == 0) g_partial[it * Nk + row] = red[0];
}

// ================= kernel 6: final loss reduction =================
__global__ __launch_bounds__(256) void k_loss(float* __restrict__ lossout) {
    __shared__ float red[256];
    int t = threadIdx.x;
    float denom = g_denom[0];
    for (int it = 0; it < NITER; ++it) {
        red[t] = g_partial[it * Nk + t];
        __syncthreads();
        for (int o = 128; o > 0; o >>= 1) { if (t < o) red[t] += red[t + o]; __syncthreads(); }
        if (t == 0) lossout[it] = red[0] / denom;
        __syncthreads();
    }
}

extern "C" void kernel_launch(void* const* d_in, const int* in_sizes, int n_in,
                              void* d_out, int out_size) {
    const float* x  = (const float*)d_in[0];
    const float* y  = (const float*)d_in[1];
    const float* We = (const float*)d_in[2];
    const float* be = (const float*)d_in[3];
    const float* Wd = (const float*)d_in[4];
    const float* bd = (const float*)d_in[5];
    float* out = (float*)d_out;
    float* losses = out + (out_size - NITER);

    k_xele<<<Nk, 256>>>(x, y);
    k_enc<<<Nk / RPB, 256>>>(We, be);
    k_denom<<<1, 1024>>>(y);
    for (int it = 0; it < NITER; ++it) {
        k_topk<<<Nk, 256>>>(it);
        k_dec<<<Nk, 384>>>(Wd, bd, x, y, out, it);
    }
    k_loss<<<1, 256>>>(losses);
}

// round 2
// speedup vs baseline: 2.0228x; 2.0228x over previous
#include <cuda_runtime.h>
#include <math.h>

#define Bk 2
#define Tk 128
#define Dk 384
#define Nk (Bk*Tk)        // 256 token rows
#define Hk 1024
#define Ck 256
#define NITER 4
#define PADk (Dk-1)       // 383
#define Sk (2*Dk-1)       // 767 shifts
#define EPSk 1e-6f
#define TEMPERk 10.0f
#define MASKVAL 1e-10f

// ---------------- scratch (no allocations allowed) ----------------
__device__ float g_xele[Nk*Dk];
__device__ float g_h[Nk*Hk];
__device__ float g_partial[NITER*Nk];
__device__ float g_denom[1];

// orderable key: larger float -> larger unsigned
__device__ __forceinline__ unsigned fkey(float f) {
    unsigned u = __float_as_uint(f);
    return (u & 0x80000000u) ? ~u : (u | 0x80000000u);
}

// ================= kernel 1: shift/argmax/attn -> x_ele =================
__global__ __launch_bounds__(256) void k_xele(const float* __restrict__ x,
                                              const float* __restrict__ y) {
    int row = blockIdx.x;
    int t = threadIdx.x;
    __shared__ float xs[Dk], ys[Dk], xa[Dk];
    __shared__ float red[256];
    __shared__ int   redi[256];

    const float* xr = x + (size_t)row * Dk;
    const float* yr = y + (size_t)row * Dk;
    for (int i = t; i < Dk; i += 256) { xs[i] = xr[i]; ys[i] = yr[i]; }
    __syncthreads();

    // qn = ||y||
    float s = 0.f;
    for (int i = t; i < Dk; i += 256) { float v = ys[i]; s += v * v; }
    red[t] = s; __syncthreads();
    for (int o = 128; o > 0; o >>= 1) { if (t < o) red[t] += red[t + o]; __syncthreads(); }
    float qn = sqrtf(red[0]);
    __syncthreads();

    // shifts: sim + argmax (first occurrence of max, like jnp.argmax)
    float bestv = -INFINITY; int bests = 0x7fffffff;
    for (int sft = t; sft < Sk; sft += 256) {
        int u0 = sft - PADk; if (u0 < 0) u0 = 0;
        int u1 = sft;        if (u1 > Dk - 1) u1 = Dk - 1;
        float dot = 0.f, ss = 0.f;
        int off = PADk - sft;
        for (int u = u0; u <= u1; ++u) {
            float xv = xs[u];
            dot += xv * ys[u + off];
            ss  += xv * xv;
        }
        float sim = dot / (qn * sqrtf(ss) + EPSk);
        if (isnan(sim)) sim = 0.f;
        if (sim > bestv || (sim == bestv && sft < bests)) { bestv = sim; bests = sft; }
    }
    red[t] = bestv; redi[t] = bests; __syncthreads();
    for (int o = 128; o > 0; o >>= 1) {
        if (t < o) {
            float vo = red[t + o]; int io = redi[t + o];
            if (vo > red[t] || (vo == red[t] && io < redi[t])) { red[t] = vo; redi[t] = io; }
        }
        __syncthreads();
    }
    int theta = redi[0];
    __syncthreads();
    int shift = theta - PADk;   // x_opt[j] = x[j+shift] (0 if OOB)

    // ||x_opt||
    float ns = 0.f;
    for (int j = t; j < Dk; j += 256) {
        int u = j + shift;
        float v = (u >= 0 && u < Dk) ? xs[u] : 0.f;
        ns += v * v;
    }
    red[t] = ns; __syncthreads();
    for (int o = 128; o > 0; o >>= 1) { if (t < o) red[t] += red[t + o]; __syncthreads(); }
    float dn = sqrtf(red[0]) * qn + EPSk;
    __syncthreads();

    // softmax((x_opt*y/dn)/TEMPER) over D
    float zmax = -INFINITY;
    for (int j = t; j < Dk; j += 256) {
        int u = j + shift;
        float v = (u >= 0 && u < Dk) ? xs[u] : 0.f;
        float z = (v * ys[j] / dn) / TEMPERk;
        zmax = fmaxf(zmax, z);
    }
    red[t] = zmax; __syncthreads();
    for (int o = 128; o > 0; o >>= 1) { if (t < o) red[t] = fmaxf(red[t], red[t + o]); __syncthreads(); }
    float m = red[0];
    __syncthreads();

    float esum = 0.f;
    for (int j = t; j < Dk; j += 256) {
        int u = j + shift;
        float v = (u >= 0 && u < Dk) ? xs[u] : 0.f;
        float z = (v * ys[j] / dn) / TEMPERk;
        float e = expf(z - m);
        esum += e;
        xa[j] = v * e;     // divide by sum later
    }
    red[t] = esum; __syncthreads();
    for (int o = 128; o > 0; o >>= 1) { if (t < o) red[t] += red[t + o]; __syncthreads(); }
    float ssum = red[0];
    __syncthreads();
    for (int j = t; j < Dk; j += 256) xa[j] = xa[j] / ssum;  // x_attn
    __syncthreads();

    // reverse shift: x_ele[j] = x_attn[j - shift]
    float* xe = g_xele + (size_t)row * Dk;
    for (int j = t; j < Dk; j += 256) {
        int u = j - shift;
        xe[j] = (u >= 0 && u < Dk) ? xa[u] : 0.f;
    }
}

// ================= kernel 2: h = x_ele @ W_enc + b_enc =================
// grid 128 = 32 rowgroups(8 rows) x 4 colgroups(256 cols), 256 threads
__global__ __launch_bounds__(256) void k_enc(const float* __restrict__ We,
                                             const float* __restrict__ be) {
    int rg = blockIdx.x >> 2;
    int cg = blockIdx.x & 3;
    int t  = threadIdx.x;
    int col = cg * 256 + t;
    __shared__ __align__(16) float xs[8 * Dk];
    for (int i = t; i < 8 * Dk; i += 256) xs[i] = g_xele[(size_t)rg * 8 * Dk + i];
    __syncthreads();

    float acc[8];
    float b = be[col];
    #pragma unroll
    for (int r = 0; r < 8; ++r) acc[r] = b;

    for (int k = 0; k < Dk; k += 4) {
        float w0 = We[(size_t)(k + 0) * Hk + col];
        float w1 = We[(size_t)(k + 1) * Hk + col];
        float w2 = We[(size_t)(k + 2) * Hk + col];
        float w3 = We[(size_t)(k + 3) * Hk + col];
        #pragma unroll
        for (int r = 0; r < 8; ++r) {
            float4 xv = *(const float4*)&xs[r * Dk + k];
            acc[r] += xv.x * w0;
            acc[r] += xv.y * w1;
            acc[r] += xv.z * w2;
            acc[r] += xv.w * w3;
        }
    }
    #pragma unroll
    for (int r = 0; r < 8; ++r)
        g_h[(size_t)(rg * 8 + r) * Hk + col] = acc[r];
}

// ================= kernel 3: denom = count(y != 0) =================
__global__ __launch_bounds__(1024) void k_denom(const float* __restrict__ y) {
    __shared__ int red[1024];
    int t = threadIdx.x;
    int c = 0;
    for (int i = t; i < Nk * Dk; i += 1024) c += (y[i] != 0.0f);
    red[t] = c; __syncthreads();
    for (int o = 512; o > 0; o >>= 1) { if (t < o) red[t] += red[t + o]; __syncthreads(); }
    if (t == 0) g_denom[0] = (float)red[0];
}

// ========== kernel 4 (fused): 4x [mask -> radix top-256] -> union decode -> loss ==========
// one block per row, 384 threads
__global__ __launch_bounds__(384) void k_fused(const float* __restrict__ Wd,
                                               const float* __restrict__ bd,
                                               const float* __restrict__ x,
                                               const float* __restrict__ y,
                                               float* __restrict__ out) {
    int row = blockIdx.x;
    int t = threadIdx.x;

    __shared__ float    hs[Hk];
    __shared__ unsigned kv[Hk];
    __shared__ int      ulist[Hk];       // byte-row offsets j*Dk
    __shared__ float4   uval[Hk];        // per-union-entry values for 4 iters
    __shared__ int      selhist[Hk];     // bit it = selected at iter it
    __shared__ int      cnt[256];
    __shared__ int      sc[256];
    __shared__ float4   red4[512];
    __shared__ int      sh_b, sh_k, sh_U;

    const float* hr = g_h + (size_t)row * Hk;
    for (int i = t; i < Hk; i += 384) { hs[i] = hr[i]; selhist[i] = 0; }
    __syncthreads();

    // ---- 4 dependent top-k selections ----
    for (int it = 0; it < NITER; ++it) {
        for (int i = t; i < Hk; i += 384) {
            float v = (it > 0 && selhist[i]) ? MASKVAL : hs[i];
            kv[i] = fkey(v);
        }
        __syncthreads();

        unsigned prefix = 0, pmask = 0; int k = Ck;
        for (int pass = 3; pass >= 0; --pass) {
            int sb = pass * 8;
            if (t < 256) cnt[t] = 0;
            __syncthreads();
            for (int i = t; i < Hk; i += 384) {
                unsigned u = kv[i];
                if ((u & pmask) == prefix) atomicAdd(&cnt[(u >> sb) & 0xff], 1);
            }
            __syncthreads();
            // parallel inclusive suffix-sum of cnt
            for (int o = 1; o < 256; o <<= 1) {
                int add = (t < 256 && t + o < 256) ? cnt[t + o] : 0;
                __syncthreads();
                if (t < 256) cnt[t] += add;
                __syncthreads();
            }
            if (t < 256) {
                int suf  = cnt[t];
                int suf1 = (t < 255) ? cnt[t + 1] : 0;
                if (suf >= k && suf1 < k) { sh_b = t; sh_k = k - suf1; }
            }
            __syncthreads();
            prefix |= ((unsigned)sh_b) << sb;
            k = sh_k;
            pmask |= (0xffu << sb);
            __syncthreads();
        }
        unsigned Tkey = prefix;   // key of 256th largest; k = #equals to keep (lowest index)

        // tie-break by ascending index: owner threads t<256 hold elems [4t,4t+4)
        int eq[4], gt_[4]; int eqc = 0;
        if (t < 256) {
            #pragma unroll
            for (int q = 0; q < 4; ++q) {
                unsigned u = kv[t * 4 + q];
                eq[q]  = (u == Tkey);
                gt_[q] = (u >  Tkey);
                eqc += eq[q];
            }
            sc[t] = eqc;
        }
        __syncthreads();
        for (int o = 1; o < 256; o <<= 1) {
            int add = (t < 256 && t >= o) ? sc[t - o] : 0;
            __syncthreads();
            if (t < 256) sc[t] += add;
            __syncthreads();
        }
        if (t < 256) {
            int eqbase = sc[t] - eqc;
            int le = 0;
            #pragma unroll
            for (int q = 0; q < 4; ++q) {
                int s = gt_[q] || (eq[q] && (eqbase + le) < k);
                le += eq[q];
                if (s) selhist[t * 4 + q] |= (1 << it);
            }
        }
        __syncthreads();
    }

    // ---- union compaction + per-iter value build ----
    int uc = 0; 
    if (t < 256) {
        #pragma unroll
        for (int q = 0; q < 4; ++q) uc += (selhist[t * 4 + q] != 0);
        sc[t] = uc;
    }
    __syncthreads();
    for (int o = 1; o < 256; o <<= 1) {
        int add = (t < 256 && t >= o) ? sc[t - o] : 0;
        __syncthreads();
        if (t < 256) sc[t] += add;
        __syncthreads();
    }
    if (t == 255) sh_U = sc[255];
    if (t < 256) {
        int p = sc[t] - uc;
        #pragma unroll
        for (int q = 0; q < 4; ++q) {
            int j = t * 4 + q;
            int s = selhist[j];
            if (s) {
                float hv_ = hs[j];
                float4 v;
                v.x = (s & 1) ?  hv_ : 0.f;
                v.y = (s & 2) ? ((s & 1) ? MASKVAL : hv_) : 0.f;
                v.z = (s & 4) ? ((s & 3) ? MASKVAL : hv_) : 0.f;
                v.w = (s & 8) ? ((s & 7) ? MASKVAL : hv_) : 0.f;
                ulist[p] = j * Dk;
                uval[p]  = v;
                ++p;
            }
        }
    }
    __syncthreads();
    int U = sh_U;

    // ---- decode: thread t owns output column t for all 4 iters ----
    float bdt = bd[t];
    float a0 = bdt, a1 = bdt, a2 = bdt, a3 = bdt;
    const float* Wt = Wd + t;
    int i = 0;
    for (; i + 4 <= U; i += 4) {
        int j0 = ulist[i], j1 = ulist[i + 1], j2 = ulist[i + 2], j3 = ulist[i + 3];
        float w0 = Wt[j0], w1 = Wt[j1], w2 = Wt[j2], w3 = Wt[j3];
        float4 v0 = uval[i], v1 = uval[i + 1], v2 = uval[i + 2], v3 = uval[i + 3];
        a0 += v0.x * w0; a1 += v0.y * w0; a2 += v0.z * w0; a3 += v0.w * w0;
        a0 += v1.x * w1; a1 += v1.y * w1; a2 += v1.z * w1; a3 += v1.w * w1;
        a0 += v2.x * w2; a1 += v2.y * w2; a2 += v2.z * w2; a3 += v2.w * w2;
        a0 += v3.x * w3; a1 += v3.y * w3; a2 += v3.z * w3; a3 += v3.w * w3;
    }
    for (; i < U; ++i) {
        int j = ulist[i];
        float w = Wt[j];
        float4 v = uval[i];
        a0 += v.x * w; a1 += v.y * w; a2 += v.z * w; a3 += v.w * w;
    }

    // ---- write outputs + masked-MSE partial (all 4 iters at once) ----
    float xv = x[(size_t)row * Dk + t];
    float yv = y[(size_t)row * Dk + t];
    out[((size_t)0 * Nk + row) * Dk + t] = a0;
    out[((size_t)1 * Nk + row) * Dk + t] = a1;
    out[((size_t)2 * Nk + row) * Dk + t] = a2;
    out[((size_t)3 * Nk + row) * Dk + t] = a3;

    float4 d;
    if (yv != 0.0f) {
        float e0 = a0 - xv, e1 = a1 - xv, e2 = a2 - xv, e3 = a3 - xv;
        d.x = e0 * e0; d.y = e1 * e1; d.z = e2 * e2; d.w = e3 * e3;
    } else {
        d.x = d.y = d.z = d.w = 0.f;
    }
    red4[t] = d;
    if (t < 128) { float4 z; z.x = z.y = z.z = z.w = 0.f; red4[Dk + t] = z; }
    __syncthreads();
    for (int o = 256; o > 0; o >>= 1) {
        if (t < o) {
            float4 a = red4[t], b = red4[t + o];
            a.x += b.x; a.y += b.y; a.z += b.z; a.w += b.w;
            red4[t] = a;
        }
        __syncthreads();
    }
    if (t == 0) {
        float4 r = red4[0];
        g_partial[0 * Nk + row] = r.x;
        g_partial[1 * Nk + row] = r.y;
        g_partial[2 * Nk + row] = r.z;
        g_partial[3 * Nk + row] = r.w;
    }
}

// ================= kernel 5: final loss reduction =================
__global__ __launch_bounds__(256) void k_loss(float* __restrict__ lossout) {
    __shared__ float red[256];
    int t = threadIdx.x;
    float denom = g_denom[0];
    for (int it = 0; it < NITER; ++it) {
        red[t] = g_partial[it * Nk + t];
        __syncthreads();
        for (int o = 128; o > 0; o >>= 1) { if (t < o) red[t] += red[t + o]; __syncthreads(); }
        if (t == 0) lossout[it] = red[0] / denom;
        __syncthreads();
    }
}

extern "C" void kernel_launch(void* const* d_in, const int* in_sizes, int n_in,
                              void* d_out, int out_size) {
    const float* x  = (const float*)d_in[0];
    const float* y  = (const float*)d_in[1];
    const float* We = (const float*)d_in[2];
    const float* be = (const float*)d_in[3];
    const float* Wd = (const float*)d_in[4];
    const float* bd = (const float*)d_in[5];
    float* out = (float*)d_out;
    float* losses = out + (out_size - NITER);

    k_xele<<<Nk, 256>>>(x, y);
    k_enc<<<128, 256>>>(We, be);
    k_denom<<<1, 1024>>>(y);
    k_fused<<<Nk, 384>>>(Wd, bd, x, y, out);
    k_loss<<<1, 256>>>(losses);
}

// round 3
// speedup vs baseline: 2.1036x; 1.0399x over previous
#include <cuda_runtime.h>
#include <math.h>

#define Bk 2
#define Tk 128
#define Dk 384
#define Nk (Bk*Tk)        // 256 token rows
#define Hk 1024
#define Ck 256
#define NITER 4
#define PADk (Dk-1)       // 383
#define Sk (2*Dk-1)       // 767 shifts
#define EPSk 1e-6f
#define TEMPERk 10.0f
#define MASKVAL 1e-10f
#define FULLMASK 0xffffffffu

// ---------------- scratch (no allocations allowed) ----------------
__device__ float g_xele[Nk*Dk];
__device__ float g_h[Nk*Hk];
__device__ float g_partial[NITER*Nk];
__device__ float g_denom[1];

// orderable key: larger float -> larger unsigned
__device__ __forceinline__ unsigned fkey(float f) {
    unsigned u = __float_as_uint(f);
    return (u & 0x80000000u) ? ~u : (u | 0x80000000u);
}

// ---- block reductions for 384 threads (12 warps), sw must hold >=12 floats ----
__device__ __forceinline__ float brsum(float v, float* sw) {
    int t = threadIdx.x;
    #pragma unroll
    for (int o = 16; o > 0; o >>= 1) v += __shfl_down_sync(FULLMASK, v, o);
    if ((t & 31) == 0) sw[t >> 5] = v;
    __syncthreads();
    if (t < 32) {
        float x = (t < 12) ? sw[t] : 0.f;
        #pragma unroll
        for (int o = 16; o > 0; o >>= 1) x += __shfl_down_sync(FULLMASK, x, o);
        if (t == 0) sw[0] = x;
    }
    __syncthreads();
    float r = sw[0];
    __syncthreads();
    return r;
}
__device__ __forceinline__ float brmax(float v, float* sw) {
    int t = threadIdx.x;
    #pragma unroll
    for (int o = 16; o > 0; o >>= 1) v = fmaxf(v, __shfl_down_sync(FULLMASK, v, o));
    if ((t & 31) == 0) sw[t >> 5] = v;
    __syncthreads();
    if (t < 32) {
        float x = (t < 12) ? sw[t] : -INFINITY;
        #pragma unroll
        for (int o = 16; o > 0; o >>= 1) x = fmaxf(x, __shfl_down_sync(FULLMASK, x, o));
        if (t == 0) sw[0] = x;
    }
    __syncthreads();
    float r = sw[0];
    __syncthreads();
    return r;
}
// argmax with first-index tiebreak; sw>=12 floats, si>=12 ints; returns index
__device__ __forceinline__ int brargmax(float v, int idx, float* sw, int* si) {
    int t = threadIdx.x;
    #pragma unroll
    for (int o = 16; o > 0; o >>= 1) {
        float vo = __shfl_down_sync(FULLMASK, v, o);
        int   io = __shfl_down_sync(FULLMASK, idx, o);
        if (vo > v || (vo == v && io < idx)) { v = vo; idx = io; }
    }
    if ((t & 31) == 0) { sw[t >> 5] = v; si[t >> 5] = idx; }
    __syncthreads();
    if (t < 32) {
        float x = (t < 12) ? sw[t] : -INFINITY;
        int   i = (t < 12) ? si[t] : 0x7fffffff;
        #pragma unroll
        for (int o = 16; o > 0; o >>= 1) {
            float vo = __shfl_down_sync(FULLMASK, x, o);
            int   io = __shfl_down_sync(FULLMASK, i, o);
            if (vo > x || (vo == x && io < i)) { x = vo; i = io; }
        }
        if (t == 0) si[0] = i;
    }
    __syncthreads();
    int r = si[0];
    __syncthreads();
    return r;
}

// ================= kernel 1: shift/argmax/attn -> x_ele (384 thr) =================
__global__ __launch_bounds__(384) void k_xele(const float* __restrict__ x,
                                              const float* __restrict__ y) {
    int row = blockIdx.x;
    int t = threadIdx.x;
    __shared__ __align__(16) float xp[1152];   // zero-padded x: xp[i]=x[i-PADk]
    __shared__ __align__(16) float ys[Dk];
    __shared__ float xa[Dk];
    __shared__ float sw[12];
    __shared__ int   si[12];

    const float* xr = x + (size_t)row * Dk;
    const float* yr = y + (size_t)row * Dk;
    xp[t] = 0.f; xp[t + 384] = 0.f; xp[t + 768] = 0.f;
    ys[t] = yr[t];
    __syncthreads();
    xp[PADk + t] = xr[t];
    __syncthreads();

    float yv_t = ys[t];
    float qn = sqrtf(brsum(yv_t * yv_t, sw));

    // two shifts per thread: sA=t, sB=t+384 (sB>=767 reads zeros, excluded below)
    int sA = t, sB = t + 384;
    float dotA = 0.f, ssA = 0.f, dotB = 0.f, ssB = 0.f;
    const float4* ys4 = (const float4*)ys;
    #pragma unroll 4
    for (int j = 0; j < Dk; j += 4) {
        float4 yv = ys4[j >> 2];
        float a0 = xp[sA + j], a1 = xp[sA + j + 1], a2 = xp[sA + j + 2], a3 = xp[sA + j + 3];
        float b0 = xp[sB + j], b1 = xp[sB + j + 1], b2 = xp[sB + j + 2], b3 = xp[sB + j + 3];
        dotA += a0 * yv.x + a1 * yv.y + a2 * yv.z + a3 * yv.w;
        ssA  += a0 * a0 + a1 * a1 + a2 * a2 + a3 * a3;
        dotB += b0 * yv.x + b1 * yv.y + b2 * yv.z + b3 * yv.w;
        ssB  += b0 * b0 + b1 * b1 + b2 * b2 + b3 * b3;
    }
    float simA = dotA / (qn * sqrtf(ssA) + EPSk);
    float simB = dotB / (qn * sqrtf(ssB) + EPSk);
    if (isnan(simA)) simA = 0.f;
    if (isnan(simB)) simB = 0.f;
    float bv = simA; int bi = sA;
    if (sB < Sk && (simB > bv)) { bv = simB; bi = sB; }   // sB>sA so tie keeps sA
    int theta = brargmax(bv, bi, sw, si);
    int shift = theta - PADk;

    // x_opt[t] = xp[t + theta]
    float v = xp[t + theta];
    float no = brsum(v * v, sw);
    float dn = sqrtf(no) * qn + EPSk;

    float z = (v * yv_t / dn) / TEMPERk;
    float m = brmax(z, sw);
    float e = expf(z - m);
    float ssum = brsum(e, sw);
    xa[t] = v * e / ssum;           // x_attn
    __syncthreads();

    // x_ele[t] = x_attn[t - shift]
    int u = t - shift;
    g_xele[(size_t)row * Dk + t] = (u >= 0 && u < Dk) ? xa[u] : 0.f;
}

// ================= kernel 2: h = x_ele @ W_enc + b_enc =================
// grid 128 = 32 rowgroups(8 rows) x 4 colgroups(256 cols), 256 threads
__global__ __launch_bounds__(256) void k_enc(const float* __restrict__ We,
                                             const float* __restrict__ be) {
    int rg = blockIdx.x >> 2;
    int cg = blockIdx.x & 3;
    int t  = threadIdx.x;
    int col = cg * 256 + t;
    __shared__ __align__(16) float xs[8 * Dk];
    for (int i = t; i < 8 * Dk; i += 256) xs[i] = g_xele[(size_t)rg * 8 * Dk + i];
    __syncthreads();

    float acc[8];
    float b = be[col];
    #pragma unroll
    for (int r = 0; r < 8; ++r) acc[r] = b;

    for (int k = 0; k < Dk; k += 4) {
        float w0 = We[(size_t)(k + 0) * Hk + col];
        float w1 = We[(size_t)(k + 1) * Hk + col];
        float w2 = We[(size_t)(k + 2) * Hk + col];
        float w3 = We[(size_t)(k + 3) * Hk + col];
        #pragma unroll
        for (int r = 0; r < 8; ++r) {
            float4 xv = *(const float4*)&xs[r * Dk + k];
            acc[r] += xv.x * w0;
            acc[r] += xv.y * w1;
            acc[r] += xv.z * w2;
            acc[r] += xv.w * w3;
        }
    }
    #pragma unroll
    for (int r = 0; r < 8; ++r)
        g_h[(size_t)(rg * 8 + r) * Hk + col] = acc[r];
}

// ================= kernel 3: denom = count(y != 0) =================
__global__ __launch_bounds__(1024) void k_denom(const float* __restrict__ y) {
    __shared__ int red[1024];
    int t = threadIdx.x;
    int c = 0;
    for (int i = t; i < Nk * Dk; i += 1024) c += (y[i] != 0.0f);
    red[t] = c; __syncthreads();
    for (int o = 512; o > 0; o >>= 1) { if (t < o) red[t] += red[t + o]; __syncthreads(); }
    if (t == 0) g_denom[0] = (float)red[0];
}

// ========== kernel 4 (fused): 4x [radix top-256] -> union decode -> loss ==========
// one block per row, 384 threads
__global__ __launch_bounds__(384) void k_fused(const float* __restrict__ Wd,
                                               const float* __restrict__ bd,
                                               const float* __restrict__ x,
                                               const float* __restrict__ y,
                                               float* __restrict__ out) {
    int row = blockIdx.x;
    int t = threadIdx.x;
    int lane = t & 31;

    __shared__ float    hs[Hk];
    __shared__ unsigned kv[Hk];
    __shared__ int      ulist[Hk];       // row offsets j*Dk
    __shared__ float4   uval[Hk];        // per-union-entry values for 4 iters
    __shared__ int      selhist[Hk];     // bit it = selected at iter it
    __shared__ int      cnt[256];
    __shared__ int      sc[256];
    __shared__ float4   red4[512];
    __shared__ unsigned sh_prefix;
    __shared__ int      sh_k, sh_U;

    const unsigned MASKKEY = fkey(MASKVAL);

    const float* hr = g_h + (size_t)row * Hk;
    // initial keys (iter 0 unmasked); elements i = t, t+384, t+768
    {
        float v0 = hr[t];           hs[t] = v0;           kv[t] = fkey(v0);           selhist[t] = 0;
        float v1 = hr[t + 384];     hs[t + 384] = v1;     kv[t + 384] = fkey(v1);     selhist[t + 384] = 0;
        if (t < 256) {
            float v2 = hr[t + 768]; hs[t + 768] = v2;     kv[t + 768] = fkey(v2);     selhist[t + 768] = 0;
        }
    }
    __syncthreads();

    // ---- 4 dependent top-k selections ----
    for (int it = 0; it < NITER; ++it) {
        if (t == 0) { sh_prefix = 0; sh_k = Ck; }
        __syncthreads();

        unsigned pmask = 0;
        for (int pass = 3; pass >= 0; --pass) {
            int sb = pass * 8;
            unsigned prefix = sh_prefix;
            if (t < 256) cnt[t] = 0;
            __syncthreads();

            // warp-aggregated histogram over elements matching current prefix
            #pragma unroll
            for (int ch = 0; ch < 3; ++ch) {
                int i = t + ch * 384;
                int bucket = -1;
                if (i < Hk) {
                    unsigned u = kv[i];
                    if ((u & pmask) == prefix) bucket = (int)((u >> sb) & 0xffu);
                }
                unsigned same = __match_any_sync(FULLMASK, bucket);
                if (bucket >= 0 && lane == (__ffs(same) - 1))
                    atomicAdd(&cnt[bucket], __popc(same));
            }
            __syncthreads();

            // warp 0: suffix-scan of cnt[256] + bucket pick
            if (t < 32) {
                int k = sh_k;
                int base = t * 8;
                int c[8], s[8];
                #pragma unroll
                for (int q = 0; q < 8; ++q) c[q] = cnt[base + q];
                s[7] = c[7];
                #pragma unroll
                for (int q = 6; q >= 0; --q) s[q] = s[q + 1] + c[q];
                int tot = s[0];
                int suf = tot;
                #pragma unroll
                for (int o = 1; o < 32; o <<= 1) {
                    int vv = __shfl_down_sync(FULLMASK, suf, o);
                    if (t + o < 32) suf += vv;
                }
                int basev = suf - tot;   // suffix over lanes > t
                #pragma unroll
                for (int q = 0; q < 8; ++q) {
                    int sq = basev + s[q];
                    int sn = (q < 7) ? basev + s[q + 1] : basev;
                    if (sq >= k && sn < k) {
                        sh_prefix = prefix | ((unsigned)(base + q) << sb);
                        sh_k = k - sn;
                    }
                }
            }
            pmask |= (0xffu << sb);
            __syncthreads();
        }
        unsigned Tkey = sh_prefix;
        int k = sh_k;    // #equals to keep, lowest index first

        // tie-break by ascending index; owner t<256 holds elems [4t, 4t+4)
        int eq[4], gt_[4]; int eqc = 0;
        if (t < 256) {
            #pragma unroll
            for (int q = 0; q < 4; ++q) {
                unsigned u = kv[t * 4 + q];
                eq[q]  = (u == Tkey);
                gt_[q] = (u >  Tkey);
                eqc += eq[q];
            }
            sc[t] = eqc;
        }
        __syncthreads();
        // warp 0: exclusive prefix scan of sc[256]
        if (t < 32) {
            int base = t * 8;
            int v[8], inc[8];
            int run = 0;
            #pragma unroll
            for (int q = 0; q < 8; ++q) { v[q] = sc[base + q]; run += v[q]; inc[q] = run; }
            int tot = run, pre = tot;
            #pragma unroll
            for (int o = 1; o < 32; o <<= 1) {
                int vv = __shfl_up_sync(FULLMASK, pre, o);
                if (t >= o) pre += vv;
            }
            int basev = pre - tot;
            #pragma unroll
            for (int q = 0; q < 8; ++q) sc[base + q] = basev + inc[q] - v[q];
        }
        __syncthreads();
        if (t < 256) {
            int eqbase = sc[t];
            int le = 0;
            #pragma unroll
            for (int q = 0; q < 4; ++q) {
                int j = t * 4 + q;
                int s = gt_[q] || (eq[q] && (eqbase + le) < k);
                le += eq[q];
                if (s) { selhist[j] |= (1 << it); kv[j] = MASKKEY; }
            }
        }
        __syncthreads();
    }

    // ---- union compaction + per-iter value build ----
    int uc = 0;
    if (t < 256) {
        #pragma unroll
        for (int q = 0; q < 4; ++q) uc += (selhist[t * 4 + q] != 0);
        sc[t] = uc;
    }
    __syncthreads();
    if (t < 32) {
        int base = t * 8;
        int v[8], inc[8];
        int run = 0;
        #pragma unroll
        for (int q = 0; q < 8; ++q) { v[q] = sc[base + q]; run += v[q]; inc[q] = run; }
        int tot = run, pre = tot;
        #pragma unroll
        for (int o = 1; o < 32; o <<= 1) {
            int vv = __shfl_up_sync(FULLMASK, pre, o);
            if (t >= o) pre += vv;
        }
        int basev = pre - tot;
        #pragma unroll
        for (int q = 0; q < 8; ++q) sc[base + q] = basev + inc[q] - v[q];
        if (t == 31) sh_U = basev + inc[7];
    }
    __syncthreads();
    if (t < 256) {
        int p = sc[t];
        #pragma unroll
        for (int q = 0; q < 4; ++q) {
            int j = t * 4 + q;
            int s = selhist[j];
            if (s) {
                float hv_ = hs[j];
                float4 v;
                v.x = (s & 1) ?  hv_ : 0.f;
                v.y = (s & 2) ? ((s & 1) ? MASKVAL : hv_) : 0.f;
                v.z = (s & 4) ? ((s & 3) ? MASKVAL : hv_) : 0.f;
                v.w = (s & 8) ? ((s & 7) ? MASKVAL : hv_) : 0.f;
                ulist[p] = j * Dk;
                uval[p]  = v;
                ++p;
            }
        }
    }
    __syncthreads();
    int U = sh_U;

    // ---- decode: thread t owns output column t for all 4 iters ----
    float bdt = bd[t];
    float a0 = bdt, a1 = bdt, a2 = bdt, a3 = bdt;
    const float* Wt = Wd + t;
    int i = 0;
    for (; i + 4 <= U; i += 4) {
        int j0 = ulist[i], j1 = ulist[i + 1], j2 = ulist[i + 2], j3 = ulist[i + 3];
        float w0 = Wt[j0], w1 = Wt[j1], w2 = Wt[j2], w3 = Wt[j3];
        float4 v0 = uval[i], v1 = uval[i + 1], v2 = uval[i + 2], v3 = uval[i + 3];
        a0 += v0.x * w0; a1 += v0.y * w0; a2 += v0.z * w0; a3 += v0.w * w0;
        a0 += v1.x * w1; a1 += v1.y * w1; a2 += v1.z * w1; a3 += v1.w * w1;
        a0 += v2.x * w2; a1 += v2.y * w2; a2 += v2.z * w2; a3 += v2.w * w2;
        a0 += v3.x * w3; a1 += v3.y * w3; a2 += v3.z * w3; a3 += v3.w * w3;
    }
    for (; i < U; ++i) {
        int j = ulist[i];
        float w = Wt[j];
        float4 v = uval[i];
        a0 += v.x * w; a1 += v.y * w; a2 += v.z * w; a3 += v.w * w;
    }

    // ---- write outputs + masked-MSE partial (all 4 iters at once) ----
    float xv = x[(size_t)row * Dk + t];
    float yv = y[(size_t)row * Dk + t];
    out[((size_t)0 * Nk + row) * Dk + t] = a0;
    out[((size_t)1 * Nk + row) * Dk + t] = a1;
    out[((size_t)2 * Nk + row) * Dk + t] = a2;
    out[((size_t)3 * Nk + row) * Dk + t] = a3;

    float4 d;
    if (yv != 0.0f) {
        float e0 = a0 - xv, e1 = a1 - xv, e2 = a2 - xv, e3 = a3 - xv;
        d.x = e0 * e0; d.y = e1 * e1; d.z = e2 * e2; d.w = e3 * e3;
    } else {
        d.x = d.y = d.z = d.w = 0.f;
    }
    red4[t] = d;
    if (t < 128) { float4 z; z.x = z.y = z.z = z.w = 0.f; red4[Dk + t] = z; }
    __syncthreads();
    for (int o = 256; o > 0; o >>= 1) {
        if (t < o) {
            float4 a = red4[t], b = red4[t + o];
            a.x += b.x; a.y += b.y; a.z += b.z; a.w += b.w;
            red4[t] = a;
        }
        __syncthreads();
    }
    if (t == 0) {
        float4 r = red4[0];
        g_partial[0 * Nk + row] = r.x;
        g_partial[1 * Nk + row] = r.y;
        g_partial[2 * Nk + row] = r.z;
        g_partial[3 * Nk + row] = r.w;
    }
}

// ================= kernel 5: final loss reduction =================
__global__ __launch_bounds__(256) void k_loss(float* __restrict__ lossout) {
    __shared__ float red[256];
    int t = threadIdx.x;
    float denom = g_denom[0];
    for (int it = 0; it < NITER; ++it) {
        red[t] = g_partial[it * Nk + t];
        __syncthreads();
        for (int o = 128; o > 0; o >>= 1) { if (t < o) red[t] += red[t + o]; __syncthreads(); }
        if (t == 0) lossout[it] = red[0] / denom;
        __syncthreads();
    }
}

extern "C" void kernel_launch(void* const* d_in, const int* in_sizes, int n_in,
                              void* d_out, int out_size) {
    const float* x  = (const float*)d_in[0];
    const float* y  = (const float*)d_in[1];
    const float* We = (const float*)d_in[2];
    const float* be = (const float*)d_in[3];
    const float* Wd = (const float*)d_in[4];
    const float* bd = (const float*)d_in[5];
    float* out = (float*)d_out;
    float* losses = out + (out_size - NITER);

    k_xele<<<Nk, 384>>>(x, y);
    k_enc<<<128, 256>>>(We, be);
    k_denom<<<1, 1024>>>(y);
    k_fused<<<Nk, 384>>>(Wd, bd, x, y, out);
    k_loss<<<1, 256>>>(losses);
}